// round 1
// baseline (speedup 1.0000x reference)
#include <cuda_runtime.h>

#define N_NODES 50000
#define N_EDGES 1600000
#define D       128
#define DHID    256
#define BM      32
#define LN_EPS  1e-5f

// scratch: aggregated edge features per node
__device__ float g_agg[N_NODES * D];
__device__ int   g_idx_is64;

// ---------------------------------------------------------------------------
// 0) detect whether edge_index is int64 or int32 (jax x64-default ambiguity)
// ---------------------------------------------------------------------------
__global__ void detect_idx_kernel(const void* __restrict__ edge_index) {
    if (threadIdx.x == 0 && blockIdx.x == 0) {
        const long long* p64 = (const long long*)edge_index;
        int ok64 = 1;
        #pragma unroll 1
        for (int i = 0; i < 64; i++) {
            long long v = p64[i];
            if (v < 0 || v >= N_NODES) ok64 = 0;
        }
        g_idx_is64 = ok64;
    }
}

// ---------------------------------------------------------------------------
// 1) zero the aggregation buffer
// ---------------------------------------------------------------------------
__global__ void zero_agg_kernel() {
    int i = blockIdx.x * blockDim.x + threadIdx.x;
    if (i < N_NODES * D / 4)
        ((float4*)g_agg)[i] = make_float4(0.f, 0.f, 0.f, 0.f);
}

// ---------------------------------------------------------------------------
// 2) scatter-sum edge_attr onto destination nodes (edge_index row 1)
//    one thread = one float4 of one edge; vector L2 reduction
// ---------------------------------------------------------------------------
__global__ void scatter_kernel(const void* __restrict__ edge_index,
                               const float* __restrict__ edge_attr) {
    long long idx = (long long)blockIdx.x * blockDim.x + threadIdx.x;
    if (idx >= (long long)N_EDGES * (D / 4)) return;
    int e  = (int)(idx >> 5);   // D/4 = 32 quads per edge
    int c4 = (int)(idx & 31);

    long long dst;
    if (g_idx_is64) {
        dst = ((const long long*)edge_index)[N_EDGES + e];
    } else {
        dst = (long long)((const int*)edge_index)[N_EDGES + e];
    }

    float4 v = ((const float4*)edge_attr)[(long long)e * (D / 4) + c4];
    float* a = &g_agg[dst * D + c4 * 4];
    asm volatile("red.global.add.v4.f32 [%0], {%1,%2,%3,%4};"
                 :: "l"(a), "f"(v.x), "f"(v.y), "f"(v.z), "f"(v.w)
                 : "memory");
}

// ---------------------------------------------------------------------------
// 3) fused MLP + LayerNorm + residual, 32 nodes per block, 256 threads
//    smem: s_cat[32][256] (32KB) | s_h1[32][256] (32KB); s_out aliases s_cat
// ---------------------------------------------------------------------------
__global__ __launch_bounds__(256) void mlp_kernel(
    const float* __restrict__ x,
    const float* __restrict__ W1, const float* __restrict__ b1,
    const float* __restrict__ W2, const float* __restrict__ b2,
    const float* __restrict__ gamma, const float* __restrict__ beta,
    float* __restrict__ out)
{
    extern __shared__ float smem[];
    float* s_cat = smem;              // [BM][2D] = [32][256]
    float* s_h1  = smem + BM * 2 * D; // [BM][DHID] = [32][256]
    float* s_out = smem;              // reuse s_cat region after GEMM1

    const int tid   = threadIdx.x;
    const int node0 = blockIdx.x * BM;

    // ---- load cat = [x | agg] tile (float4 vectorized, coalesced) ----
    #pragma unroll
    for (int r = 0; r < 8; r++) {
        int lin = r * 256 + tid;       // float4 index over BM*64
        int row = lin >> 6;
        int c4  = lin & 63;
        int node = node0 + row;
        float4 v = make_float4(0.f, 0.f, 0.f, 0.f);
        if (node < N_NODES) {
            if (c4 < 32) v = ((const float4*)x)[(long long)node * 32 + c4];
            else         v = ((const float4*)g_agg)[(long long)node * 32 + (c4 - 32)];
        }
        ((float4*)s_cat)[row * 64 + c4] = v;
    }
    __syncthreads();

    // ---- GEMM1: h1 = silu(cat @ W1 + b1), thread j owns column j ----
    {
        const int j = tid;
        float acc[BM];
        const float bj = b1[j];
        #pragma unroll
        for (int m = 0; m < BM; m++) acc[m] = bj;

        for (int k0 = 0; k0 < 2 * D; k0 += 4) {
            float4 w;
            w.x = W1[(k0 + 0) * DHID + j];
            w.y = W1[(k0 + 1) * DHID + j];
            w.z = W1[(k0 + 2) * DHID + j];
            w.w = W1[(k0 + 3) * DHID + j];
            #pragma unroll
            for (int m = 0; m < BM; m++) {
                float4 c = ((const float4*)(s_cat + m * 2 * D))[k0 >> 2];
                acc[m] = fmaf(c.x, w.x,
                          fmaf(c.y, w.y,
                           fmaf(c.z, w.z,
                            fmaf(c.w, w.w, acc[m]))));
            }
        }
        #pragma unroll
        for (int m = 0; m < BM; m++) {
            float a = acc[m];
            float s = a / (1.f + __expf(-a));   // silu
            s_h1[m * DHID + j] = s;
        }
    }
    __syncthreads();

    // ---- GEMM2: o = h1 @ W2 + b2, thread (half, j) owns 16 rows of col j ----
    {
        const int j    = tid & 127;
        const int half = tid >> 7;
        float acc2[16];
        const float bj = b2[j];
        #pragma unroll
        for (int m = 0; m < 16; m++) acc2[m] = bj;

        const float* h1b = s_h1 + (half * 16) * DHID;
        for (int k0 = 0; k0 < DHID; k0 += 4) {
            float4 w;
            w.x = W2[(k0 + 0) * D + j];
            w.y = W2[(k0 + 1) * D + j];
            w.z = W2[(k0 + 2) * D + j];
            w.w = W2[(k0 + 3) * D + j];
            #pragma unroll
            for (int m = 0; m < 16; m++) {
                float4 h = ((const float4*)(h1b + m * DHID))[k0 >> 2];
                acc2[m] = fmaf(h.x, w.x,
                           fmaf(h.y, w.y,
                            fmaf(h.z, w.z,
                             fmaf(h.w, w.w, acc2[m]))));
            }
        }
        #pragma unroll
        for (int m = 0; m < 16; m++)
            s_out[(half * 16 + m) * D + j] = acc2[m];
    }
    __syncthreads();

    // ---- LayerNorm + residual: one warp per row, 4 rows per warp ----
    {
        const int warp = tid >> 5;
        const int lane = tid & 31;
        #pragma unroll
        for (int rr = 0; rr < 4; rr++) {
            int row  = warp + rr * 8;
            int node = node0 + row;
            float v0 = s_out[row * D + lane];
            float v1 = s_out[row * D + lane + 32];
            float v2 = s_out[row * D + lane + 64];
            float v3 = s_out[row * D + lane + 96];
            float sum = v0 + v1 + v2 + v3;
            float sq  = v0 * v0 + v1 * v1 + v2 * v2 + v3 * v3;
            #pragma unroll
            for (int o = 16; o > 0; o >>= 1) {
                sum += __shfl_xor_sync(0xffffffffu, sum, o);
                sq  += __shfl_xor_sync(0xffffffffu, sq,  o);
            }
            float mean = sum * (1.f / D);
            float var  = sq * (1.f / D) - mean * mean;
            float rstd = rsqrtf(var + LN_EPS);
            if (node < N_NODES) {
                long long base = (long long)node * D;
                float g0 = gamma[lane],      b0 = beta[lane];
                float g1 = gamma[lane + 32], b1v = beta[lane + 32];
                float g2 = gamma[lane + 64], b2v = beta[lane + 64];
                float g3 = gamma[lane + 96], b3v = beta[lane + 96];
                out[base + lane]      = x[base + lane]      + (v0 - mean) * rstd * g0 + b0;
                out[base + lane + 32] = x[base + lane + 32] + (v1 - mean) * rstd * g1 + b1v;
                out[base + lane + 64] = x[base + lane + 64] + (v2 - mean) * rstd * g2 + b2v;
                out[base + lane + 96] = x[base + lane + 96] + (v3 - mean) * rstd * g3 + b3v;
            }
        }
    }
}

// ---------------------------------------------------------------------------
extern "C" void kernel_launch(void* const* d_in, const int* in_sizes, int n_in,
                              void* d_out, int out_size)
{
    const float* x          = (const float*)d_in[0];
    const void*  edge_index = d_in[1];
    const float* edge_attr  = (const float*)d_in[2];
    const float* W1         = (const float*)d_in[3];
    const float* b1         = (const float*)d_in[4];
    const float* W2         = (const float*)d_in[5];
    const float* b2         = (const float*)d_in[6];
    const float* gamma      = (const float*)d_in[7];
    const float* beta       = (const float*)d_in[8];
    float* out = (float*)d_out;

    cudaFuncSetAttribute(mlp_kernel,
                         cudaFuncAttributeMaxDynamicSharedMemorySize, 65536);

    detect_idx_kernel<<<1, 32>>>(edge_index);

    zero_agg_kernel<<<(N_NODES * D / 4 + 255) / 256, 256>>>();

    long long total = (long long)N_EDGES * (D / 4);
    scatter_kernel<<<(unsigned)((total + 255) / 256), 256>>>(edge_index, edge_attr);

    mlp_kernel<<<(N_NODES + BM - 1) / BM, 256, 65536>>>(
        x, W1, b1, W2, b2, gamma, beta, out);
}

// round 2
// speedup vs baseline: 1.1645x; 1.1645x over previous
#include <cuda_runtime.h>

#define N_NODES 50000
#define N_EDGES 1600000
#define D       128
#define DHID    256
#define BM      32
#define LN_EPS  1e-5f

// scratch: aggregated edge features per node
__device__ float g_agg[N_NODES * D];
__device__ int   g_idx_is64;

// ---------------------------------------------------------------------------
// 0) detect whether edge_index is int64 or int32 (jax x64-default ambiguity)
// ---------------------------------------------------------------------------
__global__ void detect_idx_kernel(const void* __restrict__ edge_index) {
    if (threadIdx.x == 0 && blockIdx.x == 0) {
        const long long* p64 = (const long long*)edge_index;
        int ok64 = 1;
        #pragma unroll 1
        for (int i = 0; i < 64; i++) {
            long long v = p64[i];
            if (v < 0 || v >= N_NODES) ok64 = 0;
        }
        g_idx_is64 = ok64;
    }
}

// ---------------------------------------------------------------------------
// 1) zero the aggregation buffer
// ---------------------------------------------------------------------------
__global__ void zero_agg_kernel() {
    int i = blockIdx.x * blockDim.x + threadIdx.x;
    if (i < N_NODES * D / 4)
        ((float4*)g_agg)[i] = make_float4(0.f, 0.f, 0.f, 0.f);
}

// ---------------------------------------------------------------------------
// 2) scatter-sum edge_attr onto destination nodes (edge_index row 1)
//    one warp = one edge (32 float4 quads); vector L2 reduction
// ---------------------------------------------------------------------------
__global__ void scatter_kernel(const void* __restrict__ edge_index,
                               const float* __restrict__ edge_attr) {
    long long idx = (long long)blockIdx.x * blockDim.x + threadIdx.x;
    if (idx >= (long long)N_EDGES * (D / 4)) return;
    int e  = (int)(idx >> 5);   // D/4 = 32 quads per edge
    int c4 = (int)(idx & 31);

    long long dst;
    if (g_idx_is64) {
        dst = ((const long long*)edge_index)[N_EDGES + e];
    } else {
        dst = (long long)((const int*)edge_index)[N_EDGES + e];
    }

    float4 v = ((const float4*)edge_attr)[(long long)e * (D / 4) + c4];
    float* a = &g_agg[dst * D + c4 * 4];
    asm volatile("red.global.add.v4.f32 [%0], {%1,%2,%3,%4};"
                 :: "l"(a), "f"(v.x), "f"(v.y), "f"(v.z), "f"(v.w)
                 : "memory");
}

// ---------------------------------------------------------------------------
// 3) fused MLP + LayerNorm + residual, 32 nodes per block, 256 threads
//    TN=2 register tiling: each thread owns an adjacent column PAIR, W loaded
//    as float2 (LDG.64), halving L1 wavefronts per FFMA vs round-1 version.
//    smem: s_cat[32][256] (32KB) | s_h1[32][256] (32KB); s_out aliases s_cat
// ---------------------------------------------------------------------------
__global__ __launch_bounds__(256, 3) void mlp_kernel(
    const float* __restrict__ x,
    const float* __restrict__ W1, const float* __restrict__ b1,
    const float* __restrict__ W2, const float* __restrict__ b2,
    const float* __restrict__ gamma, const float* __restrict__ beta,
    float* __restrict__ out)
{
    extern __shared__ float smem[];
    float* s_cat = smem;              // [BM][2D] = [32][256]
    float* s_h1  = smem + BM * 2 * D; // [BM][DHID] = [32][256]
    float* s_out = smem;              // reuse s_cat region after GEMM1

    const int tid   = threadIdx.x;
    const int node0 = blockIdx.x * BM;

    // ---- load cat = [x | agg] tile (float4 vectorized, coalesced) ----
    #pragma unroll
    for (int r = 0; r < 8; r++) {
        int lin = r * 256 + tid;       // float4 index over BM*64
        int row = lin >> 6;
        int c4  = lin & 63;
        int node = node0 + row;
        float4 v = make_float4(0.f, 0.f, 0.f, 0.f);
        if (node < N_NODES) {
            if (c4 < 32) v = ((const float4*)x)[(long long)node * 32 + c4];
            else         v = ((const float4*)g_agg)[(long long)node * 32 + (c4 - 32)];
        }
        ((float4*)s_cat)[row * 64 + c4] = v;
    }
    __syncthreads();

    // ---- GEMM1: h1 = silu(cat @ W1 + b1) ----
    // thread = (mh, jj): columns {2jj, 2jj+1}, rows [mh*16, mh*16+16)
    {
        const int jj = tid & 127;
        const int mh = tid >> 7;       // 0 or 1
        const int c0 = 2 * jj;

        float2 bj = *(const float2*)&b1[c0];
        float acc[16][2];
        #pragma unroll
        for (int m = 0; m < 16; m++) { acc[m][0] = bj.x; acc[m][1] = bj.y; }

        const float* catb = s_cat + (mh * 16) * 2 * D;

        for (int k0 = 0; k0 < 2 * D; k0 += 4) {
            float2 w0 = *(const float2*)&W1[(k0 + 0) * DHID + c0];
            float2 w1 = *(const float2*)&W1[(k0 + 1) * DHID + c0];
            float2 w2 = *(const float2*)&W1[(k0 + 2) * DHID + c0];
            float2 w3 = *(const float2*)&W1[(k0 + 3) * DHID + c0];
            #pragma unroll
            for (int m = 0; m < 16; m++) {
                float4 c = ((const float4*)(catb + m * 2 * D))[k0 >> 2];
                acc[m][0] = fmaf(c.x, w0.x, fmaf(c.y, w1.x,
                            fmaf(c.z, w2.x, fmaf(c.w, w3.x, acc[m][0]))));
                acc[m][1] = fmaf(c.x, w0.y, fmaf(c.y, w1.y,
                            fmaf(c.z, w2.y, fmaf(c.w, w3.y, acc[m][1]))));
            }
        }
        #pragma unroll
        for (int m = 0; m < 16; m++) {
            float a0 = acc[m][0], a1 = acc[m][1];
            float2 s;
            s.x = a0 / (1.f + __expf(-a0));
            s.y = a1 / (1.f + __expf(-a1));
            *(float2*)&s_h1[(mh * 16 + m) * DHID + c0] = s;
        }
    }
    __syncthreads();

    // ---- GEMM2: o = h1 @ W2 + b2 ----
    // thread = (mg, jj): columns {2jj, 2jj+1} of D=128, rows [mg*8, mg*8+8)
    {
        const int jj = tid & 63;
        const int mg = tid >> 6;       // 0..3
        const int c0 = 2 * jj;

        float2 bj = *(const float2*)&b2[c0];
        float acc2[8][2];
        #pragma unroll
        for (int m = 0; m < 8; m++) { acc2[m][0] = bj.x; acc2[m][1] = bj.y; }

        const float* h1b = s_h1 + (mg * 8) * DHID;

        for (int k0 = 0; k0 < DHID; k0 += 4) {
            float2 w0 = *(const float2*)&W2[(k0 + 0) * D + c0];
            float2 w1 = *(const float2*)&W2[(k0 + 1) * D + c0];
            float2 w2 = *(const float2*)&W2[(k0 + 2) * D + c0];
            float2 w3 = *(const float2*)&W2[(k0 + 3) * D + c0];
            #pragma unroll
            for (int m = 0; m < 8; m++) {
                float4 h = ((const float4*)(h1b + m * DHID))[k0 >> 2];
                acc2[m][0] = fmaf(h.x, w0.x, fmaf(h.y, w1.x,
                             fmaf(h.z, w2.x, fmaf(h.w, w3.x, acc2[m][0]))));
                acc2[m][1] = fmaf(h.x, w0.y, fmaf(h.y, w1.y,
                             fmaf(h.z, w2.y, fmaf(h.w, w3.y, acc2[m][1]))));
            }
        }
        #pragma unroll
        for (int m = 0; m < 8; m++) {
            float2 o; o.x = acc2[m][0]; o.y = acc2[m][1];
            *(float2*)&s_out[(mg * 8 + m) * D + c0] = o;
        }
    }
    __syncthreads();

    // ---- LayerNorm + residual: one warp per row, 4 rows per warp ----
    {
        const int warp = tid >> 5;
        const int lane = tid & 31;
        #pragma unroll
        for (int rr = 0; rr < 4; rr++) {
            int row  = warp + rr * 8;
            int node = node0 + row;
            float v0 = s_out[row * D + lane];
            float v1 = s_out[row * D + lane + 32];
            float v2 = s_out[row * D + lane + 64];
            float v3 = s_out[row * D + lane + 96];
            float sum = v0 + v1 + v2 + v3;
            float sq  = v0 * v0 + v1 * v1 + v2 * v2 + v3 * v3;
            #pragma unroll
            for (int o = 16; o > 0; o >>= 1) {
                sum += __shfl_xor_sync(0xffffffffu, sum, o);
                sq  += __shfl_xor_sync(0xffffffffu, sq,  o);
            }
            float mean = sum * (1.f / D);
            float var  = sq * (1.f / D) - mean * mean;
            float rstd = rsqrtf(var + LN_EPS);
            if (node < N_NODES) {
                long long base = (long long)node * D;
                float g0 = gamma[lane],      b0 = beta[lane];
                float g1 = gamma[lane + 32], b1v = beta[lane + 32];
                float g2 = gamma[lane + 64], b2v = beta[lane + 64];
                float g3 = gamma[lane + 96], b3v = beta[lane + 96];
                out[base + lane]      = x[base + lane]      + (v0 - mean) * rstd * g0 + b0;
                out[base + lane + 32] = x[base + lane + 32] + (v1 - mean) * rstd * g1 + b1v;
                out[base + lane + 64] = x[base + lane + 64] + (v2 - mean) * rstd * g2 + b2v;
                out[base + lane + 96] = x[base + lane + 96] + (v3 - mean) * rstd * g3 + b3v;
            }
        }
    }
}

// ---------------------------------------------------------------------------
extern "C" void kernel_launch(void* const* d_in, const int* in_sizes, int n_in,
                              void* d_out, int out_size)
{
    const float* x          = (const float*)d_in[0];
    const void*  edge_index = d_in[1];
    const float* edge_attr  = (const float*)d_in[2];
    const float* W1         = (const float*)d_in[3];
    const float* b1         = (const float*)d_in[4];
    const float* W2         = (const float*)d_in[5];
    const float* b2         = (const float*)d_in[6];
    const float* gamma      = (const float*)d_in[7];
    const float* beta       = (const float*)d_in[8];
    float* out = (float*)d_out;

    cudaFuncSetAttribute(mlp_kernel,
                         cudaFuncAttributeMaxDynamicSharedMemorySize, 65536);

    detect_idx_kernel<<<1, 32>>>(edge_index);

    zero_agg_kernel<<<(N_NODES * D / 4 + 255) / 256, 256>>>();

    long long total = (long long)N_EDGES * (D / 4);
    scatter_kernel<<<(unsigned)((total + 255) / 256), 256>>>(edge_index, edge_attr);

    mlp_kernel<<<(N_NODES + BM - 1) / BM, 256, 65536>>>(
        x, W1, b1, W2, b2, gamma, beta, out);
}